// round 15
// baseline (speedup 1.0000x reference)
#include <cuda_runtime.h>
#include <cstdint>
#include <cstddef>

#define NORB   9
#define NATOMS 384
#define NEDGES 6144
#define NKP    4
#define ALLN   (NATOMS * NORB)              // 3456
#define NFEAT  58
#define KELEM  (ALLN * ALLN)                // 11,943,936 floats per k-region
#define NCPLX  ((size_t)NKP * KELEM)        // 47,775,744
#define NITEM  (NEDGES + NATOMS)            // 6528
#define TWO_PI 6.283185307179586f

// 64-byte chunks (16 floats, 4 float4)
#define CHUNKS (NCPLX / 16)                 // 2,985,984
#define CPR    (ALLN / 16)                  // 216 chunks per matrix row
#define CPK    (KELEM / 16)                 // 746,496 chunks per k-region

// k_main grid: scatter blocks first, then fill blocks.
#define SCATB_PER_K 1479                    // 1479*256 = 6528*58 exact
#define NSCATB (SCATB_PER_K * NKP)          // 5916
#define NFILLB ((int)(NCPLX / 4 / 1024))    // 11664 exact: block = 1024 float4
#define NGRID  (NSCATB + NFILLB)            // 17580

// Static feature -> (row, col, factor) maps for upper-tri orbital pairs
// l = [0,1,2], dims = [1,3,5], offsets = [0,1,4]
__constant__ unsigned char cROWS[NFEAT] = {
    0,
    0,0,0,
    0,0,0,0,0,
    1,1,1,2,2,2,3,3,3,
    1,1,1,1,1,2,2,2,2,2,3,3,3,3,3,
    4,4,4,4,4,5,5,5,5,5,6,6,6,6,6,7,7,7,7,7,8,8,8,8,8
};
__constant__ unsigned char cCOLS[NFEAT] = {
    0,
    1,2,3,
    4,5,6,7,8,
    1,2,3,1,2,3,1,2,3,
    4,5,6,7,8,4,5,6,7,8,4,5,6,7,8,
    4,5,6,7,8,4,5,6,7,8,4,5,6,7,8,4,5,6,7,8,4,5,6,7,8
};
__constant__ float cFACS[NFEAT] = {
    0.5f,
    1.f,1.f,1.f,
    1.f,1.f,1.f,1.f,1.f,
    0.5f,0.5f,0.5f,0.5f,0.5f,0.5f,0.5f,0.5f,0.5f,
    1.f,1.f,1.f,1.f,1.f,1.f,1.f,1.f,1.f,1.f,1.f,1.f,1.f,1.f,1.f,
    0.5f,0.5f,0.5f,0.5f,0.5f,0.5f,0.5f,0.5f,0.5f,0.5f,0.5f,0.5f,0.5f,
    0.5f,0.5f,0.5f,0.5f,0.5f,0.5f,0.5f,0.5f,0.5f,0.5f,0.5f,0.5f
};

// Chunk bitmap: 1 byte per 64B output chunk (~3 MB static scratch).
__device__ unsigned char g_bm[CHUNKS];

// Zero the bitmap (186,624 uint4 = 729*256 exact).
__global__ void k_bmz() {
    ((uint4*)g_bm)[blockIdx.x * 256 + threadIdx.x] = make_uint4(0u,0u,0u,0u);
}

// Mark every 64B chunk that receives any contribution. Thread = (item, k).
__global__ void k_mark(const int* __restrict__ eidx) {
    const int t = blockIdx.x * blockDim.x + threadIdx.x;
    if (t >= NITEM * NKP) return;
    const int w = t >> 2;
    const int k = t & 3;

    int a, b;
    if (w < NEDGES) { a = eidx[w]; b = eidx[NEDGES + w]; }
    else            { a = w - NEDGES; b = a; }
    if ((unsigned)a >= NATOMS || (unsigned)b >= NATOMS) return;

    const int kbase = k * CPK;
    #pragma unroll
    for (int r = 0; r < NORB; ++r) {
        {   // block (a,b): rows a*9+r, cols [b*9, b*9+9)
            const int base = kbase + (a * NORB + r) * CPR;
            g_bm[base + ((b * NORB)     >> 4)] = 1;
            g_bm[base + ((b * NORB + 8) >> 4)] = 1;
        }
        {   // block (b,a): rows b*9+r, cols [a*9, a*9+9)
            const int base = kbase + (b * NORB + r) * CPR;
            g_bm[base + ((a * NORB)     >> 4)] = 1;
            g_bm[base + ((a * NORB + 8) >> 4)] = 1;
        }
    }
}

// Zero exactly the marked chunks (~5%, ~12 MB unique). Leaves them L2-hot
// for the REDs in k_main. Thread = one float4; warp covers 512B contiguous.
__global__ void k_zmark(float4* __restrict__ out4, int pass) {
    // Each pass covers CHUNKS/4 float4s (one quarter of the space per launch
    // would be wasteful; instead one kernel, thread per float4 over a strided
    // sweep): q = global float4 index.
    const size_t q = (size_t)(blockIdx.x) * 256 + threadIdx.x
                   + (size_t)pass * 0;     // single pass; pass unused
    // grid sized to cover all float4s exactly
    const int chunk = (int)(q >> 2);
    if (g_bm[chunk])
        out4[q] = make_float4(0.f, 0.f, 0.f, 0.f);
}

// Main kernel: scatter blocks RED into marked (pre-zeroed, L2-hot) chunks;
// fill blocks zero the unmarked chunks with warp-contiguous stores. The two
// halves are address-disjoint -> no synchronization, full overlap.
__global__ __launch_bounds__(256) void k_main(
    const float* __restrict__ hop,     // [E, 58]
    const float* __restrict__ ons,     // [N, 58]
    const float* __restrict__ kpts,    // [4, 3]
    const int*   __restrict__ eidx,    // [2, E]
    const int*   __restrict__ eshift,  // [E, 3]
    float*       __restrict__ out)     // [4, 3456, 3456] float32 (real part)
{
    const int bid = blockIdx.x;
    const int tid = threadIdx.x;

    if (bid < NSCATB) {
        // ---------- scatter (exact R5 structure: proven 19.8us) ----------
        const int k = bid / SCATB_PER_K;
        const int t = (bid - k * SCATB_PER_K) * 256 + tid;   // exact 6528*58
        const int w = t / NFEAT;
        const int f = t - w * NFEAT;
        const bool is_edge = (w < NEDGES);

        int ai, aj;
        float ph;                        // Re[exp(-2*pi*i k.R)]
        if (is_edge) {
            ai = eidx[w];
            aj = eidx[NEDGES + w];
            const float d = kpts[k * 3 + 0] * (float)eshift[w * 3 + 0]
                          + kpts[k * 3 + 1] * (float)eshift[w * 3 + 1]
                          + kpts[k * 3 + 2] * (float)eshift[w * 3 + 2];
            ph = __cosf(TWO_PI * d);
        } else {
            ai = w - NEDGES;
            aj = ai;
            ph = 1.f;
        }
        if ((unsigned)ai >= NATOMS || (unsigned)aj >= NATOMS) return;

        const float* __restrict__ src =
            is_edge ? (hop + (size_t)w * NFEAT)
                    : (ons + (size_t)(w - NEDGES) * NFEAT);
        const float v = cFACS[f] * src[f] * ph;

        const int r = ai * NORB + (int)cROWS[f];
        const int c = aj * NORB + (int)cCOLS[f];
        float* __restrict__ base = out + (size_t)k * KELEM;
        atomicAdd(base + (size_t)r * ALLN + c, v);   // Re(B)   at (r,c)
        atomicAdd(base + (size_t)c * ALLN + r, v);   // Re(B^H) at (c,r)
    } else {
        // ---------- fill unmarked chunks, warp-contiguous ----------
        // Block owns 1024 consecutive float4 (16 KB). Store instruction u
        // covers float4 indices [qbase + u*256, qbase + u*256 + 256): each
        // warp writes 512B contiguous per instruction (ideal coalescing).
        const size_t qbase = (size_t)(bid - NSCATB) * 1024;
        float4* __restrict__ out4 = (float4*)out;
        const float4 z = make_float4(0.f, 0.f, 0.f, 0.f);
        #pragma unroll
        for (int u = 0; u < 4; ++u) {
            const size_t q = qbase + u * 256 + tid;
            if (!g_bm[q >> 2])           // marked chunks owned by zmark+REDs
                out4[q] = z;
        }
    }
}

// ---- complex64 fallback (unused for the f32 output; kept for safety) ----
__global__ __launch_bounds__(256, 8) void hr2hk_scatter_cplx(
    const float* __restrict__ hop, const float* __restrict__ ons,
    const float* __restrict__ kpts, const int* __restrict__ eidx,
    const int* __restrict__ eshift, float* __restrict__ out)
{
    const int w = blockIdx.x;
    const int t = threadIdx.x;
    if (t >= NFEAT * NKP) return;
    const int f = t >> 2;
    const int k = t & 3;
    const bool is_edge = (w < NEDGES);

    int ai, aj;
    float pre, pim;
    if (is_edge) {
        ai = eidx[w];
        aj = eidx[NEDGES + w];
        const float d = kpts[k * 3 + 0] * (float)eshift[w * 3 + 0]
                      + kpts[k * 3 + 1] * (float)eshift[w * 3 + 1]
                      + kpts[k * 3 + 2] * (float)eshift[w * 3 + 2];
        float s, c;
        __sincosf(TWO_PI * d, &s, &c);
        pre = c; pim = -s;
    } else {
        ai = w - NEDGES; aj = ai; pre = 1.f; pim = 0.f;
    }
    if ((unsigned)ai >= NATOMS || (unsigned)aj >= NATOMS) return;

    const float* __restrict__ src =
        is_edge ? (hop + (size_t)w * NFEAT)
                : (ons + (size_t)(w - NEDGES) * NFEAT);
    const float val = cFACS[f] * src[f];
    const float re = val * pre, im = val * pim;
    const int r = ai * NORB + (int)cROWS[f];
    const int c = aj * NORB + (int)cCOLS[f];
    const size_t kbase = (size_t)k * KELEM;
    float* p0 = out + 2 * (kbase + (size_t)r * ALLN + c);
    float* p1 = out + 2 * (kbase + (size_t)c * ALLN + r);
    atomicAdd(p0 + 0, re);
    atomicAdd(p0 + 1, im);
    atomicAdd(p1 + 0, re);
    atomicAdd(p1 + 1, -im);
}

__global__ void hr2hk_zero(uint4* __restrict__ out, size_t n_u4) {
    for (size_t i = (size_t)blockIdx.x * blockDim.x + threadIdx.x;
         i < n_u4; i += (size_t)gridDim.x * blockDim.x)
        out[i] = make_uint4(0u, 0u, 0u, 0u);
}

extern "C" void kernel_launch(void* const* d_in, const int* in_sizes, int n_in,
                              void* d_out, int out_size) {
    // Identify inputs by (pairwise-distinct) element counts, not position.
    const float* hop    = nullptr;
    const float* ons    = nullptr;
    const float* kpts   = nullptr;
    const int*   eidx   = nullptr;
    const int*   eshift = nullptr;

    for (int i = 0; i < n_in; ++i) {
        switch (in_sizes[i]) {
            case NEDGES * NFEAT: hop    = (const float*)d_in[i]; break;  // 356352
            case NATOMS * NFEAT: ons    = (const float*)d_in[i]; break;  // 22272
            case NKP * 3:        kpts   = (const float*)d_in[i]; break;  // 12
            case 2 * NEDGES:     eidx   = (const int*)d_in[i];   break;  // 12288
            case NEDGES * 3:     eshift = (const int*)d_in[i];   break;  // 18432
            default: break;
        }
    }
    if (!hop || !ons || !kpts || !eidx || !eshift) return;

    if ((long long)out_size == (long long)NCPLX) {
        // f32 real-part output: bitmap prep, zero marked chunks, then one
        // grid where fill (unmarked, coalesced) and scatter (marked, REDs)
        // run concurrently on disjoint addresses.
        k_bmz<<<729, 256>>>();
        k_mark<<<(NITEM * NKP + 255) / 256, 256>>>(eidx);
        k_zmark<<<(int)(NCPLX / 4 / 256), 256>>>((float4*)d_out, 0);
        k_main<<<NGRID, 256>>>(hop, ons, kpts, eidx, eshift, (float*)d_out);
    } else if ((long long)out_size == 2LL * (long long)NCPLX) {
        hr2hk_zero<<<8192, 256>>>((uint4*)d_out, NCPLX * 8 / 16);
        hr2hk_scatter_cplx<<<NEDGES + NATOMS, 256>>>(
            hop, ons, kpts, eidx, eshift, (float*)d_out);
    }
}

// round 16
// speedup vs baseline: 1.2683x; 1.2683x over previous
#include <cuda_runtime.h>
#include <cstdint>
#include <cstddef>

#define NORB   9
#define NATOMS 384
#define NEDGES 6144
#define NKP    4
#define ALLN   (NATOMS * NORB)              // 3456
#define NFEAT  58
#define KELEM  (ALLN * ALLN)                // 11,943,936 floats per k-region
#define NCPLX  ((size_t)NKP * KELEM)        // 47,775,744
#define NITEM  (NEDGES + NATOMS)            // 6528
#define TWO_PI 6.283185307179586f

// 64-byte chunks (16 floats, 4 float4)
#define CHUNKS (NCPLX / 16)                 // 2,985,984
#define CPR    (ALLN / 16)                  // 216 chunks per matrix row
#define CPK    (KELEM / 16)                 // 746,496 chunks per k-region

// k_main: 11664 blocks; each does a 1024-float4 fill slice + ~130 scatter items.
#define NMAINB     11664                    // 11664*1024 = NCPLX/4 exact
#define TOTAL_SCAT (NITEM * NFEAT * NKP)    // 1,514,496
#define ITEMS_PER_BLOCK 130                 // 11664*130 = 1,516,320 >= TOTAL_SCAT

// k_markzero: thread = (item, k, row): 6528*4*9 = 235,008 = 918*256 exact
#define MZ_BLOCKS 918

// Static feature -> (row, col, factor) maps for upper-tri orbital pairs
// l = [0,1,2], dims = [1,3,5], offsets = [0,1,4]
__constant__ unsigned char cROWS[NFEAT] = {
    0,
    0,0,0,
    0,0,0,0,0,
    1,1,1,2,2,2,3,3,3,
    1,1,1,1,1,2,2,2,2,2,3,3,3,3,3,
    4,4,4,4,4,5,5,5,5,5,6,6,6,6,6,7,7,7,7,7,8,8,8,8,8
};
__constant__ unsigned char cCOLS[NFEAT] = {
    0,
    1,2,3,
    4,5,6,7,8,
    1,2,3,1,2,3,1,2,3,
    4,5,6,7,8,4,5,6,7,8,4,5,6,7,8,
    4,5,6,7,8,4,5,6,7,8,4,5,6,7,8,4,5,6,7,8,4,5,6,7,8
};
__constant__ float cFACS[NFEAT] = {
    0.5f,
    1.f,1.f,1.f,
    1.f,1.f,1.f,1.f,1.f,
    0.5f,0.5f,0.5f,0.5f,0.5f,0.5f,0.5f,0.5f,0.5f,
    1.f,1.f,1.f,1.f,1.f,1.f,1.f,1.f,1.f,1.f,1.f,1.f,1.f,1.f,1.f,
    0.5f,0.5f,0.5f,0.5f,0.5f,0.5f,0.5f,0.5f,0.5f,0.5f,0.5f,0.5f,0.5f,
    0.5f,0.5f,0.5f,0.5f,0.5f,0.5f,0.5f,0.5f,0.5f,0.5f,0.5f,0.5f
};

// Chunk bitmap: 1 byte per 64B output chunk (~3 MB). Zero-initialized at
// module load; k_main's fill threads self-clean it back to zero each launch.
__device__ unsigned char g_bm[CHUNKS];

// Mark + zero both chunks overlapped by one 9-float block row.
__device__ __forceinline__ void mark_zero_row(
    float* __restrict__ kbase, int bmk, int r, int clo)
{
    const int c0 = clo >> 4;
    const int c1 = (clo + 8) >> 4;
    g_bm[bmk + r * CPR + c0] = 1;
    float4* __restrict__ p = (float4*)(kbase + (size_t)r * ALLN) + c0 * 4;
    const float4 z = make_float4(0.f, 0.f, 0.f, 0.f);
    p[0] = z; p[1] = z; p[2] = z; p[3] = z;
    if (c1 != c0) {
        g_bm[bmk + r * CPR + c1] = 1;
        p[4] = z; p[5] = z; p[6] = z; p[7] = z;
    }
}

// One kernel prep: thread = (item, k, row). Marks the bitmap bytes AND
// zeroes the marked chunks (duplicate zero-writes between items are benign).
__global__ __launch_bounds__(256) void k_markzero(
    const int* __restrict__ eidx,
    float*     __restrict__ out)
{
    const int t    = blockIdx.x * 256 + threadIdx.x;   // exact 235,008
    const int item = t / (NKP * NORB);
    const int rem  = t - item * (NKP * NORB);
    const int k    = rem / NORB;
    const int row  = rem - k * NORB;

    int a, b;
    if (item < NEDGES) { a = eidx[item]; b = eidx[NEDGES + item]; }
    else               { a = item - NEDGES; b = a; }
    if ((unsigned)a >= NATOMS || (unsigned)b >= NATOMS) return;

    float* __restrict__ kbase = out + (size_t)k * KELEM;
    const int bmk = k * CPK;

    mark_zero_row(kbase, bmk, a * NORB + row, b * NORB);   // block (a,b)
    if (a != b)
        mark_zero_row(kbase, bmk, b * NORB + row, a * NORB);   // block (b,a)
}

// Main kernel: every block does BOTH jobs -> fill (unmarked chunks, warp-
// contiguous predicated stores) and scatter (threads 0..129, one (item,k,f)
// work item each, 2 REDs into marked pre-zeroed chunks). The two address
// sets are disjoint (bitmap), so no ordering is needed and the DRAM-write
// stream overlaps the LTS-atomic stream inside every resident block.
// Fill threads then self-clean their bitmap bytes for the next replay.
__global__ __launch_bounds__(256) void k_main(
    const float* __restrict__ hop,     // [E, 58]
    const float* __restrict__ ons,     // [N, 58]
    const float* __restrict__ kpts,    // [4, 3]
    const int*   __restrict__ eidx,    // [2, E]
    const int*   __restrict__ eshift,  // [E, 3]
    float*       __restrict__ out)     // [4, 3456, 3456] float32 (real part)
{
    const int bid = blockIdx.x;
    const int tid = threadIdx.x;

    // ---------- fill slice: 1024 consecutive float4 (16 KB) ----------
    const size_t qbase = (size_t)bid * 1024;
    float4* __restrict__ out4 = (float4*)out;
    const float4 z = make_float4(0.f, 0.f, 0.f, 0.f);

    size_t cidx[4];
    #pragma unroll
    for (int u = 0; u < 4; ++u) {
        const size_t q = qbase + u * 256 + tid;   // warp: 512B contiguous
        cidx[u] = q >> 2;
        if (!g_bm[cidx[u]])                        // marked: owned by REDs
            out4[q] = z;
    }

    // ---------- scatter share: threads 0..129 ----------
    if (tid < ITEMS_PER_BLOCK) {
        const int si = bid * ITEMS_PER_BLOCK + tid;
        if (si < TOTAL_SCAT) {
            const int w   = si / (NFEAT * NKP);
            const int rm  = si - w * (NFEAT * NKP);
            const int k   = rm / NFEAT;
            const int f   = rm - k * NFEAT;
            const bool is_edge = (w < NEDGES);

            int ai, aj;
            float ph;                    // Re[exp(-2*pi*i k.R)]
            if (is_edge) {
                ai = eidx[w];
                aj = eidx[NEDGES + w];
                const float d = kpts[k * 3 + 0] * (float)eshift[w * 3 + 0]
                              + kpts[k * 3 + 1] * (float)eshift[w * 3 + 1]
                              + kpts[k * 3 + 2] * (float)eshift[w * 3 + 2];
                ph = __cosf(TWO_PI * d);
            } else {
                ai = w - NEDGES;
                aj = ai;
                ph = 1.f;
            }
            if ((unsigned)ai < NATOMS && (unsigned)aj < NATOMS) {
                const float* __restrict__ src =
                    is_edge ? (hop + (size_t)w * NFEAT)
                            : (ons + (size_t)(w - NEDGES) * NFEAT);
                const float v = cFACS[f] * src[f] * ph;
                const int r = ai * NORB + (int)cROWS[f];
                const int c = aj * NORB + (int)cCOLS[f];
                float* __restrict__ base = out + (size_t)k * KELEM;
                atomicAdd(base + (size_t)r * ALLN + c, v);  // Re(B)   (r,c)
                atomicAdd(base + (size_t)c * ALLN + r, v);  // Re(B^H) (c,r)
            }
        }
    }

    // ---------- self-clean the bitmap for the next graph replay ----------
    // Safe: each 64B chunk's 4 bm-readers are 4 consecutive lanes of ONE
    // warp (lockstep: all reads above precede these stores); no other block
    // or scatter thread reads g_bm.
    #pragma unroll
    for (int u = 0; u < 4; ++u)
        g_bm[cidx[u]] = 0;
}

// ---- complex64 fallback (unused for the f32 output; kept for safety) ----
__global__ __launch_bounds__(256, 8) void hr2hk_scatter_cplx(
    const float* __restrict__ hop, const float* __restrict__ ons,
    const float* __restrict__ kpts, const int* __restrict__ eidx,
    const int* __restrict__ eshift, float* __restrict__ out)
{
    const int w = blockIdx.x;
    const int t = threadIdx.x;
    if (t >= NFEAT * NKP) return;
    const int f = t >> 2;
    const int k = t & 3;
    const bool is_edge = (w < NEDGES);

    int ai, aj;
    float pre, pim;
    if (is_edge) {
        ai = eidx[w];
        aj = eidx[NEDGES + w];
        const float d = kpts[k * 3 + 0] * (float)eshift[w * 3 + 0]
                      + kpts[k * 3 + 1] * (float)eshift[w * 3 + 1]
                      + kpts[k * 3 + 2] * (float)eshift[w * 3 + 2];
        float s, c;
        __sincosf(TWO_PI * d, &s, &c);
        pre = c; pim = -s;
    } else {
        ai = w - NEDGES; aj = ai; pre = 1.f; pim = 0.f;
    }
    if ((unsigned)ai >= NATOMS || (unsigned)aj >= NATOMS) return;

    const float* __restrict__ src =
        is_edge ? (hop + (size_t)w * NFEAT)
                : (ons + (size_t)(w - NEDGES) * NFEAT);
    const float val = cFACS[f] * src[f];
    const float re = val * pre, im = val * pim;
    const int r = ai * NORB + (int)cROWS[f];
    const int c = aj * NORB + (int)cCOLS[f];
    const size_t kbase = (size_t)k * KELEM;
    float* p0 = out + 2 * (kbase + (size_t)r * ALLN + c);
    float* p1 = out + 2 * (kbase + (size_t)c * ALLN + r);
    atomicAdd(p0 + 0, re);
    atomicAdd(p0 + 1, im);
    atomicAdd(p1 + 0, re);
    atomicAdd(p1 + 1, -im);
}

__global__ void hr2hk_zero(uint4* __restrict__ out, size_t n_u4) {
    for (size_t i = (size_t)blockIdx.x * blockDim.x + threadIdx.x;
         i < n_u4; i += (size_t)gridDim.x * blockDim.x)
        out[i] = make_uint4(0u, 0u, 0u, 0u);
}

extern "C" void kernel_launch(void* const* d_in, const int* in_sizes, int n_in,
                              void* d_out, int out_size) {
    // Identify inputs by (pairwise-distinct) element counts, not position.
    const float* hop    = nullptr;
    const float* ons    = nullptr;
    const float* kpts   = nullptr;
    const int*   eidx   = nullptr;
    const int*   eshift = nullptr;

    for (int i = 0; i < n_in; ++i) {
        switch (in_sizes[i]) {
            case NEDGES * NFEAT: hop    = (const float*)d_in[i]; break;  // 356352
            case NATOMS * NFEAT: ons    = (const float*)d_in[i]; break;  // 22272
            case NKP * 3:        kpts   = (const float*)d_in[i]; break;  // 12
            case 2 * NEDGES:     eidx   = (const int*)d_in[i];   break;  // 12288
            case NEDGES * 3:     eshift = (const int*)d_in[i];   break;  // 18432
            default: break;
        }
    }
    if (!hop || !ons || !kpts || !eidx || !eshift) return;

    if ((long long)out_size == (long long)NCPLX) {
        // f32 real-part output: one prep kernel (mark bitmap + zero marked
        // chunks), then one kernel where every block fills AND scatters.
        k_markzero<<<MZ_BLOCKS, 256>>>(eidx, (float*)d_out);
        k_main<<<NMAINB, 256>>>(hop, ons, kpts, eidx, eshift, (float*)d_out);
    } else if ((long long)out_size == 2LL * (long long)NCPLX) {
        hr2hk_zero<<<8192, 256>>>((uint4*)d_out, NCPLX * 8 / 16);
        hr2hk_scatter_cplx<<<NEDGES + NATOMS, 256>>>(
            hop, ons, kpts, eidx, eshift, (float*)d_out);
    }
}